// round 13
// baseline (speedup 1.0000x reference)
#include <cuda_runtime.h>
#include <cuda_fp16.h>
#include <math.h>
#include <stdint.h>

// Problem dims
#define Bn   8
#define Sn   256
#define Hn   768
#define Ln   20
#define LSn  8
#define En   300
#define BSn  2048            // B*S
#define MTOT 40960           // B*S*L
#define NEGV (-10000.0f)

// ---------------- scratch (static device globals; no allocs allowed) ----------------
__device__ __align__(16) float g_tkn[BSn * Hn];
__device__ __align__(16) float g_T1[BSn * Hn];
__device__ __align__(16) float g_lab[Ln * LSn * Hn];
__device__ __align__(16) float g_Lab2[Ln * LSn * Hn];
__device__ __align__(16) float g_scores[BSn * Ln * LSn];
__device__ __align__(16) float g_a[MTOT * LSn];
__device__ __align__(16) float g_bin[MTOT];
__device__ __align__(16) float g_q2c[Bn * Ln * Hn];

__device__ __align__(16) __half g_tokhi[BSn * Hn];
__device__ __align__(16) __half g_toklo[BSn * Hn];
__device__ __align__(16) __half g_tknhi[BSn * Hn];
__device__ __align__(16) __half g_tknlo[BSn * Hn];
__device__ __align__(16) __half g_W1hi[Hn * Hn];
__device__ __align__(16) __half g_W1lo[Hn * Hn];
__device__ __align__(16) __half g_W5ahi[Hn * Hn];
__device__ __align__(16) __half g_W5alo[Hn * Hn];
__device__ __align__(16) __half g_Bhi[Hn * 2 * Hn];      // W5[c|d] as [768,1536], fp16 hi
// Af stored L-MAJOR: row m' = l*2048 + bs  (hi only — single-pass big GEMM)
__device__ __align__(16) __half g_Afhi[(size_t)MTOT * 1536];   // 126 MB

__device__ __forceinline__ uint32_t smem_u32(const void* p) {
    uint32_t a;
    asm("{ .reg .u64 t; cvta.to.shared.u64 t, %1; cvt.u32.u64 %0, t; }" : "=r"(a) : "l"(p));
    return a;
}

// fp16 round of a float4 -> packed 8B
__device__ __forceinline__ uint2 pack4(float4 v) {
    __half2 p0 = __halves2half2(__float2half_rn(v.x), __float2half_rn(v.y));
    __half2 p1 = __halves2half2(__float2half_rn(v.z), __float2half_rn(v.w));
    uint2 r;
    r.x = *reinterpret_cast<uint32_t*>(&p0);
    r.y = *reinterpret_cast<uint32_t*>(&p1);
    return r;
}

// SMEM: A stage0 @0, A stage1 @18432, B stage0 @36864, B stage1 @55296
#define STAGEB 18432              // 128*72*2 bytes (row padded to 144B)
#define SMEM_SZ 73728

// ---------------------------------------------------------------------------
// fp16-split MMA GEMM: C[M,N] = A[M,K] * B[N,K]^T.  CTA tile 128x128, 256 thr.
// PASS=3: Ahi*Bhi + Alo*Bhi + Ahi*Blo (error ~2^-22)
// PASS=2: Ahi*Bhi + Alo*Bhi           (drops B-rounding term, ~1e-4)
// PASS=1: Ahi*Bhi only               (error ~1.1e-4 realized; budget 1e-3)
// MODE 0: store fp32. MODE 1: fp32 + fp16 hi/lo split to g_tknhi/lo.
// MODE 2: A rows are l-major (m' = l*2048+bs); out[bs*20+l] =
//         tanh(acc + T1[bs] + sum_t a[m,t]*Lab2[l,t] + b5)
// ---------------------------------------------------------------------------
template <int MODE, int PASS>
__global__ __launch_bounds__(256, 2) void tgemm(
    const __half* __restrict__ Ahi, const __half* __restrict__ Alo, int lda,
    const __half* __restrict__ Bhi, const __half* __restrict__ Blo, int ldb,
    float* __restrict__ C, int Kd,
    const float* __restrict__ b5)
{
    extern __shared__ char smem[];
    const uint32_t sb = smem_u32(smem);
    const int tid = threadIdx.x;
    const int wid = tid >> 5, lid = tid & 31;
    const int n0 = blockIdx.x * 128, m0 = blockIdx.y * 128;

    const int wm = wid & 1;        // 0..1  -> 64-row slab
    const int wn = wid >> 1;       // 0..3  -> 32-col slab
    const int g  = lid >> 2;       // group id
    const int t4 = lid & 3;        // thread in group

    const int arow = wm * 64 + (lid & 15);
    const int acol = (lid >> 4) * 8;
    // B x4 ldmatrix addressing (validated in R12: identical numerics):
    // lanes 0-7 -> j=2jp k-half0, 8-15 -> j=2jp k-half1, 16-23 -> j=2jp+1 k0, 24-31 -> j=2jp+1 k1
    const int b_lrow = wn * 32 + ((lid >> 4) * 8) + (lid & 7);
    const int b_kh   = ((lid >> 3) & 1) * 8;

    const int lrow = tid >> 3;
    const int lc8  = (tid & 7) * 8;

    const int NCp = Kd >> 6;
    const int NC  = NCp * PASS;

    float acc[4][4][4];
    #pragma unroll
    for (int i = 0; i < 4; i++)
        #pragma unroll
        for (int j = 0; j < 4; j++)
            #pragma unroll
            for (int r = 0; r < 4; r++) acc[i][j][r] = 0.0f;

    auto load_chunk = [&](int c, int s) {
        const int pass = (PASS == 1) ? 0 : ((c >= 2 * NCp) ? 2 : (c >= NCp ? 1 : 0));
        const int k0 = (c - pass * NCp) * 64;
        const __half* Ap = (pass == 1) ? Alo : Ahi;
        const __half* Bp = (pass == 2) ? Blo : Bhi;
        const uint32_t aB = sb + s * STAGEB;
        const uint32_t bB = sb + 36864 + s * STAGEB;
        #pragma unroll
        for (int p = 0; p < 4; p++) {
            const int row = lrow + p * 32;
            const uint32_t da = aB + (uint32_t)row * 144 + lc8 * 2;
            const void* ga = Ap + (size_t)(m0 + row) * lda + k0 + lc8;
            asm volatile("cp.async.cg.shared.global [%0], [%1], 16;" :: "r"(da), "l"(ga));
            const uint32_t db = bB + (uint32_t)row * 144 + lc8 * 2;
            const void* gb = Bp + (size_t)(n0 + row) * ldb + k0 + lc8;
            asm volatile("cp.async.cg.shared.global [%0], [%1], 16;" :: "r"(db), "l"(gb));
        }
        asm volatile("cp.async.commit_group;" ::: "memory");
    };

    auto compute = [&](int s) {
        const uint32_t aB = sb + s * STAGEB;
        const uint32_t bB = sb + 36864 + s * STAGEB;
        #pragma unroll
        for (int kk = 0; kk < 4; kk++) {
            uint32_t af[4][4], bf[4][2];
            #pragma unroll
            for (int i = 0; i < 4; i++) {
                const uint32_t ad = aB + (uint32_t)(arow + i * 16) * 144
                                  + (uint32_t)(kk * 16 + acol) * 2;
                asm volatile("ldmatrix.sync.aligned.m8n8.x4.shared.b16 {%0,%1,%2,%3}, [%4];"
                    : "=r"(af[i][0]), "=r"(af[i][1]), "=r"(af[i][2]), "=r"(af[i][3])
                    : "r"(ad));
            }
            #pragma unroll
            for (int jp = 0; jp < 2; jp++) {
                const uint32_t bd = bB + (uint32_t)(b_lrow + jp * 16) * 144
                                  + (uint32_t)(kk * 16 + b_kh) * 2;
                asm volatile("ldmatrix.sync.aligned.m8n8.x4.shared.b16 {%0,%1,%2,%3}, [%4];"
                    : "=r"(bf[jp * 2][0]), "=r"(bf[jp * 2][1]),
                      "=r"(bf[jp * 2 + 1][0]), "=r"(bf[jp * 2 + 1][1])
                    : "r"(bd));
            }
            #pragma unroll
            for (int i = 0; i < 4; i++)
                #pragma unroll
                for (int j = 0; j < 4; j++)
                    asm volatile(
                        "mma.sync.aligned.m16n8k16.row.col.f32.f16.f16.f32 "
                        "{%0,%1,%2,%3}, {%4,%5,%6,%7}, {%8,%9}, {%0,%1,%2,%3};"
                        : "+f"(acc[i][j][0]), "+f"(acc[i][j][1]),
                          "+f"(acc[i][j][2]), "+f"(acc[i][j][3])
                        : "r"(af[i][0]), "r"(af[i][1]), "r"(af[i][2]), "r"(af[i][3]),
                          "r"(bf[j][0]), "r"(bf[j][1]));
        }
    };

    load_chunk(0, 0);
    for (int c = 0; c < NC; c++) {
        if (c + 1 < NC) {
            load_chunk(c + 1, (c + 1) & 1);
            asm volatile("cp.async.wait_group 1;" ::: "memory");
        } else {
            asm volatile("cp.async.wait_group 0;" ::: "memory");
        }
        __syncthreads();
        compute(c & 1);
        __syncthreads();
    }

    // ---------------- epilogue ----------------
    if (MODE == 2) {
        const int l   = m0 >> 11;        // 128 | 2048 so each tile is one l
        const int bsb = m0 & 2047;
        float* sLab = (float*)smem;          // [8][128]
        float* sB5  = sLab + 8 * 128;        // [128]
        float* sAv  = sB5 + 128;             // [128][8]
        for (int idx = tid; idx < 1024; idx += 256) {
            const int t = idx >> 7, o = idx & 127;
            sLab[idx] = g_Lab2[(size_t)(l * LSn + t) * Hn + n0 + o];
        }
        if (tid < 128) sB5[tid] = b5[n0 + tid];
        for (int idx = tid; idx < 1024; idx += 256) {
            const int r = idx >> 3, t = idx & 7;
            sAv[idx] = g_a[((size_t)(bsb + r) * Ln + l) * LSn + t];
        }
        __syncthreads();
        #pragma unroll
        for (int i = 0; i < 4; i++) {
            #pragma unroll
            for (int j = 0; j < 4; j++) {
                const int col = wn * 32 + j * 8 + 2 * t4;
                #pragma unroll
                for (int h = 0; h < 2; h++) {
                    const int rl = wm * 64 + i * 16 + g + h * 8;
                    const int bs = bsb + rl;
                    const float2 t1 = *(const float2*)(g_T1 + (size_t)bs * Hn + n0 + col);
                    float v0 = acc[i][j][h * 2]     + t1.x + sB5[col];
                    float v1 = acc[i][j][h * 2 + 1] + t1.y + sB5[col + 1];
                    const float* av = sAv + rl * 8;
                    #pragma unroll
                    for (int t = 0; t < 8; t++) {
                        const float at = av[t];
                        v0 += at * sLab[t * 128 + col];
                        v1 += at * sLab[t * 128 + col + 1];
                    }
                    float2 res = make_float2(tanhf(v0), tanhf(v1));
                    *(float2*)(C + ((size_t)bs * Ln + l) * Hn + n0 + col) = res;
                }
            }
        }
    } else {
        #pragma unroll
        for (int i = 0; i < 4; i++) {
            #pragma unroll
            for (int j = 0; j < 4; j++) {
                const int col = wn * 32 + j * 8 + 2 * t4;
                #pragma unroll
                for (int h = 0; h < 2; h++) {
                    const int m = m0 + wm * 64 + i * 16 + g + h * 8;
                    const float v0 = acc[i][j][h * 2];
                    const float v1 = acc[i][j][h * 2 + 1];
                    *(float2*)(C + (size_t)m * Hn + n0 + col) = make_float2(v0, v1);
                    if (MODE == 1) {
                        const size_t o = (size_t)m * Hn + n0 + col;
                        __half h0 = __float2half_rn(v0);
                        __half h1 = __float2half_rn(v1);
                        __half l0 = __float2half_rn(v0 - __half2float(h0));
                        __half l1 = __float2half_rn(v1 - __half2float(h1));
                        *(__half2*)(g_tknhi + o) = __halves2half2(h0, h1);
                        *(__half2*)(g_tknlo + o) = __halves2half2(l0, l1);
                    }
                }
            }
        }
    }
}

// ---------------------------------------------------------------------------
// fp32 -> fp16 hi/lo split (strided source)
// ---------------------------------------------------------------------------
__global__ __launch_bounds__(256) void split_k(
    const float* __restrict__ src, int ld,
    __half* __restrict__ hi, __half* __restrict__ lo,
    int Mr, int Kc)
{
    int idx = blockIdx.x * 256 + threadIdx.x;
    if (idx >= Mr * Kc) return;
    int r = idx / Kc, c = idx - r * Kc;
    float x = src[(size_t)r * ld + c];
    __half h = __float2half_rn(x);
    hi[idx] = h;
    if (lo) lo[idx] = __float2half_rn(x - __half2float(h));
}

// ---------------------------------------------------------------------------
// Small guarded SGEMM, 32x32 tile (high CTA count): C[M,N] = A[M,K]*B[N,K]^T
// ---------------------------------------------------------------------------
__global__ __launch_bounds__(256) void sgemm32(
    const float* __restrict__ A, int lda,
    const float* __restrict__ Bm, int ldb,
    float* __restrict__ C, int ldc,
    int M, int N, int K)
{
    __shared__ float As[32][33];
    __shared__ float Bs[32][33];
    const int m0 = blockIdx.x * 32;
    const int n0 = blockIdx.y * 32;
    const int tid = threadIdx.x;
    const int tr = tid >> 4;     // 0..15
    const int tc = tid & 15;     // 0..15
    float acc[2][2] = {};

    for (int k0 = 0; k0 < K; k0 += 32) {
        #pragma unroll
        for (int p = 0; p < 4; p++) {
            int idx = tid + p * 256;
            int r = idx >> 5;
            int kk = idx & 31;
            int gk = k0 + kk;
            int gm = m0 + r;
            int gn = n0 + r;
            As[kk][r] = (gm < M && gk < K) ? A[(size_t)gm * lda + gk] : 0.0f;
            Bs[kk][r] = (gn < N && gk < K) ? Bm[(size_t)gn * ldb + gk] : 0.0f;
        }
        __syncthreads();
        #pragma unroll
        for (int kk = 0; kk < 32; kk++) {
            float a0 = As[kk][tr * 2], a1 = As[kk][tr * 2 + 1];
            float b0 = Bs[kk][tc * 2], b1 = Bs[kk][tc * 2 + 1];
            acc[0][0] += a0 * b0; acc[0][1] += a0 * b1;
            acc[1][0] += a1 * b0; acc[1][1] += a1 * b1;
        }
        __syncthreads();
    }
    #pragma unroll
    for (int i = 0; i < 2; i++) {
        int gm = m0 + tr * 2 + i;
        if (gm >= M) continue;
        #pragma unroll
        for (int j = 0; j < 2; j++) {
            int gn = n0 + tc * 2 + j;
            if (gn < N) C[(size_t)gm * ldc + gn] = acc[i][j];
        }
    }
}

// ---------------------------------------------------------------------------
// Softmax over label tokens + b_in
// ---------------------------------------------------------------------------
__global__ __launch_bounds__(256) void softmax_a_kernel(
    const float* __restrict__ label_mask,
    const float* __restrict__ input_mask)
{
    int m = blockIdx.x * 256 + threadIdx.x;
    if (m >= MTOT) return;
    int bs = m / Ln;
    int l = m - bs * Ln;
    float sc[LSn];
    float mx = -INFINITY;
    #pragma unroll
    for (int t = 0; t < LSn; t++) {
        float v = g_scores[(size_t)bs * (Ln * LSn) + l * LSn + t]
                + (1.0f - label_mask[l * LSn + t]) * NEGV;
        sc[t] = v;
        mx = fmaxf(mx, v);
    }
    float sum = 0.0f;
    #pragma unroll
    for (int t = 0; t < LSn; t++) { sc[t] = __expf(sc[t] - mx); sum += sc[t]; }
    float inv = 1.0f / sum;
    #pragma unroll
    for (int t = 0; t < LSn; t++) g_a[(size_t)m * LSn + t] = sc[t] * inv;
    g_bin[m] = mx + (1.0f - input_mask[bs]) * NEGV;
}

// ---------------------------------------------------------------------------
// Softmax over S + q2c
// ---------------------------------------------------------------------------
__global__ __launch_bounds__(256) void q2c_kernel()
{
    int b = blockIdx.x / Ln;
    int l = blockIdx.x - b * Ln;
    int s = threadIdx.x;
    __shared__ float red[256];
    __shared__ float w[256];

    float v = g_bin[(size_t)(b * Sn + s) * Ln + l];
    red[s] = v; __syncthreads();
    for (int off = 128; off > 0; off >>= 1) {
        if (s < off) red[s] = fmaxf(red[s], red[s + off]);
        __syncthreads();
    }
    float mx = red[0]; __syncthreads();
    float e = __expf(v - mx);
    red[s] = e; __syncthreads();
    for (int off = 128; off > 0; off >>= 1) {
        if (s < off) red[s] += red[s + off];
        __syncthreads();
    }
    float inv = 1.0f / red[0];
    w[s] = e * inv;
    __syncthreads();

    for (int h = s; h < Hn; h += 256) {
        float acc = 0.0f;
        #pragma unroll 8
        for (int ss = 0; ss < Sn; ss++)
            acc += w[ss] * g_tkn[(size_t)(b * Sn + ss) * Hn + h];
        g_q2c[(size_t)(b * Ln + l) * Hn + h] = acc;
    }
}

// ---------------------------------------------------------------------------
// Build fused A operand as fp16 (hi only), L-MAJOR rows (m' = l*2048+bs):
//   Af[m', h]      = tkn*c2q   (h in [0,768))
//   Af[m', 768+h]  = tkn*q2c
// ---------------------------------------------------------------------------
__global__ __launch_bounds__(256) void afused_kernel()
{
    int l   = blockIdx.x;
    int bs0 = blockIdx.y * 16;
    int b   = bs0 / Sn;
    int tid = threadIdx.x;

    __shared__ float labs[LSn * Hn];
    __shared__ float qv[Hn];
    __shared__ float av[16][LSn];

    for (int idx = tid; idx < LSn * Hn; idx += 256)
        labs[idx] = g_lab[(size_t)l * LSn * Hn + idx];
    for (int idx = tid; idx < Hn; idx += 256)
        qv[idx] = g_q2c[(size_t)(b * Ln + l) * Hn + idx];
    for (int idx = tid; idx < 16 * LSn; idx += 256) {
        int i = idx >> 3, t = idx & 7;
        av[i][t] = g_a[((size_t)(bs0 + i) * Ln + l) * LSn + t];
    }
    __syncthreads();

    const int hc = tid * 4;          // threads 0..191 active (192*4 = 768)
    for (int i = 0; i < 16; i++) {
        int bs = bs0 + i;
        size_t m = (size_t)l * BSn + bs;     // l-major row
        if (hc < Hn) {
            float a0 = av[i][0], a1 = av[i][1], a2 = av[i][2], a3 = av[i][3];
            float a4 = av[i][4], a5 = av[i][5], a6 = av[i][6], a7 = av[i][7];
            const float4 tv = *(const float4*)(g_tkn + (size_t)bs * Hn + hc);
            const float4 qv4 = *(const float4*)(qv + hc);
            float4 c = make_float4(0.f, 0.f, 0.f, 0.f);
            #pragma unroll
            for (int t = 0; t < LSn; t++) {
                const float at = (t == 0) ? a0 : (t == 1) ? a1 : (t == 2) ? a2 :
                                 (t == 3) ? a3 : (t == 4) ? a4 : (t == 5) ? a5 :
                                 (t == 6) ? a6 : a7;
                const float4 lb = *(const float4*)(labs + t * Hn + hc);
                c.x += at * lb.x; c.y += at * lb.y;
                c.z += at * lb.z; c.w += at * lb.w;
            }
            float4 v1 = make_float4(tv.x * c.x, tv.y * c.y, tv.z * c.z, tv.w * c.w);
            float4 v2 = make_float4(tv.x * qv4.x, tv.y * qv4.y, tv.z * qv4.z, tv.w * qv4.w);
            __half* Ah = g_Afhi + m * 1536;
            *(uint2*)(Ah + hc)      = pack4(v1);
            *(uint2*)(Ah + Hn + hc) = pack4(v2);
        }
    }
}

// ---------------------------------------------------------------------------
extern "C" void kernel_launch(void* const* d_in, const int* in_sizes, int n_in,
                              void* d_out, int out_size)
{
    const float* token = (const float*)d_in[0];
    const float* labe  = (const float*)d_in[1];
    const float* imask = (const float*)d_in[2];
    const float* lmask = (const float*)d_in[3];
    const float* W1    = (const float*)d_in[4];
    const float* W2    = (const float*)d_in[5];
    const float* W5    = (const float*)d_in[6];
    const float* b5    = (const float*)d_in[7];
    float* out = (float*)d_out;

    float *p_tkn, *p_lab, *p_T1, *p_Lab2, *p_scores;
    __half *p_tokhi, *p_toklo, *p_tknhi, *p_tknlo;
    __half *p_W1hi, *p_W1lo, *p_W5ahi, *p_W5alo, *p_Bhi, *p_Afhi;
    cudaGetSymbolAddress((void**)&p_tkn,    g_tkn);
    cudaGetSymbolAddress((void**)&p_lab,    g_lab);
    cudaGetSymbolAddress((void**)&p_T1,     g_T1);
    cudaGetSymbolAddress((void**)&p_Lab2,   g_Lab2);
    cudaGetSymbolAddress((void**)&p_scores, g_scores);
    cudaGetSymbolAddress((void**)&p_tokhi,  g_tokhi);
    cudaGetSymbolAddress((void**)&p_toklo,  g_toklo);
    cudaGetSymbolAddress((void**)&p_tknhi,  g_tknhi);
    cudaGetSymbolAddress((void**)&p_tknlo,  g_tknlo);
    cudaGetSymbolAddress((void**)&p_W1hi,   g_W1hi);
    cudaGetSymbolAddress((void**)&p_W1lo,   g_W1lo);
    cudaGetSymbolAddress((void**)&p_W5ahi,  g_W5ahi);
    cudaGetSymbolAddress((void**)&p_W5alo,  g_W5alo);
    cudaGetSymbolAddress((void**)&p_Bhi,    g_Bhi);
    cudaGetSymbolAddress((void**)&p_Afhi,   g_Afhi);

    cudaFuncSetAttribute((const void*)tgemm<0,2>, cudaFuncAttributeMaxDynamicSharedMemorySize, SMEM_SZ);
    cudaFuncSetAttribute((const void*)tgemm<1,2>, cudaFuncAttributeMaxDynamicSharedMemorySize, SMEM_SZ);
    cudaFuncSetAttribute((const void*)tgemm<2,1>, cudaFuncAttributeMaxDynamicSharedMemorySize, SMEM_SZ);

    // splits (fp16 hi/lo; W5cd hi-only)
    split_k<<<(BSn * Hn + 255) / 256, 256>>>(token, Hn, p_tokhi, p_toklo, BSn, Hn);
    split_k<<<(Hn * Hn + 255) / 256, 256>>>(W1, Hn, p_W1hi, p_W1lo, Hn, Hn);
    split_k<<<(Hn * Hn + 255) / 256, 256>>>(W5, 4 * Hn, p_W5ahi, p_W5alo, Hn, Hn);
    split_k<<<(Hn * 2 * Hn + 255) / 256, 256>>>(W5 + 2 * Hn, 4 * Hn, p_Bhi, (__half*)nullptr, Hn, 2 * Hn);

    // lab = label_embs @ W2^T   [160,768] K=300 (fp32, 120 CTAs)
    sgemm32<<<dim3(5, 24), 256>>>(labe, En, W2, En, p_lab, Hn, Ln * LSn, Hn, En);
    // tkn = token @ W1^T (HMMA 2-pass, fp32 out + fp16 hi/lo split)
    tgemm<1,2><<<dim3(6, 16), 256, SMEM_SZ>>>(p_tokhi, p_toklo, Hn, p_W1hi, p_W1lo, Hn,
                                              p_tkn, Hn, nullptr);
    // T1 = tkn @ W5a^T (HMMA 2-pass)
    tgemm<0,2><<<dim3(6, 16), 256, SMEM_SZ>>>(p_tknhi, p_tknlo, Hn, p_W5ahi, p_W5alo, Hn,
                                              p_T1, Hn, nullptr);
    // Lab2 = lab @ W5b^T   [160,768] K=768 (fp32, 120 CTAs)
    sgemm32<<<dim3(5, 24), 256>>>(p_lab, Hn, W5 + Hn, 4 * Hn, p_Lab2, Hn, Ln * LSn, Hn, Hn);
    // scores = tkn @ lab^T [2048,160] K=768 (fp32, 320 CTAs)
    sgemm32<<<dim3(64, 5), 256>>>(p_tkn, Hn, p_lab, Hn, p_scores, Ln * LSn,
                                  BSn, Ln * LSn, Hn);
    // softmaxes
    softmax_a_kernel<<<MTOT / 256, 256>>>(lmask, imask);
    q2c_kernel<<<Bn * Ln, 256>>>();
    // fused A operand (fp16 hi, l-major)
    afused_kernel<<<dim3(Ln, BSn / 16), 256>>>();
    // big fused GEMM (HMMA single-pass) + epilogue
    tgemm<2,1><<<dim3(6, 320), 256, SMEM_SZ>>>(p_Afhi, (const __half*)nullptr, 2 * Hn,
                                               p_Bhi, (const __half*)nullptr, 2 * Hn,
                                               out, 2 * Hn, b5);
}

// round 16
// speedup vs baseline: 1.4801x; 1.4801x over previous
#include <cuda_runtime.h>
#include <cuda_fp16.h>
#include <math.h>
#include <stdint.h>

// Problem dims
#define Bn   8
#define Sn   256
#define Hn   768
#define Ln   20
#define LSn  8
#define En   300
#define BSn  2048            // B*S
#define MTOT 40960           // B*S*L
#define NEGV (-10000.0f)

// ---------------- scratch (static device globals; no allocs allowed) ----------------
__device__ __align__(16) float g_tkn[BSn * Hn];
__device__ __align__(16) float g_T1[BSn * Hn];
__device__ __align__(16) float g_lab[Ln * LSn * Hn];
__device__ __align__(16) float g_Lab2[Ln * LSn * Hn];
__device__ __align__(16) float g_scores[BSn * Ln * LSn];
__device__ __align__(16) float g_a[MTOT * LSn];
__device__ __align__(16) float g_bin[MTOT];
__device__ __align__(16) float g_q2c[Bn * Ln * Hn];

__device__ __align__(16) __half g_tokhi[BSn * Hn];
__device__ __align__(16) __half g_toklo[BSn * Hn];
__device__ __align__(16) __half g_tknhi[BSn * Hn];
__device__ __align__(16) __half g_tknlo[BSn * Hn];
__device__ __align__(16) __half g_W1hi[Hn * Hn];
__device__ __align__(16) __half g_W1lo[Hn * Hn];
__device__ __align__(16) __half g_W5ahi[Hn * Hn];
__device__ __align__(16) __half g_W5alo[Hn * Hn];
__device__ __align__(16) __half g_Bhi[Hn * 2 * Hn];      // W5[c|d] as [768,1536], fp16 hi
// Af stored L-MAJOR: row m' = l*2048 + bs  (hi only — single-pass big GEMM)
__device__ __align__(16) __half g_Afhi[(size_t)MTOT * 1536];   // 126 MB

__device__ __forceinline__ uint32_t smem_u32(const void* p) {
    uint32_t a;
    asm("{ .reg .u64 t; cvta.to.shared.u64 t, %1; cvt.u32.u64 %0, t; }" : "=r"(a) : "l"(p));
    return a;
}

// fp16 round of a float4 -> packed 8B
__device__ __forceinline__ uint2 pack4(float4 v) {
    __half2 p0 = __halves2half2(__float2half_rn(v.x), __float2half_rn(v.y));
    __half2 p1 = __halves2half2(__float2half_rn(v.z), __float2half_rn(v.w));
    uint2 r;
    r.x = *reinterpret_cast<uint32_t*>(&p0);
    r.y = *reinterpret_cast<uint32_t*>(&p1);
    return r;
}

// SMEM: A stage0 @0, A stage1 @18432, B stage0 @36864, B stage1 @55296
#define STAGEB 18432              // 128*72*2 bytes (row padded to 144B)
#define SMEM_SZ 73728

// ---------------------------------------------------------------------------
// fp16-split MMA GEMM: C[M,N] = A[M,K] * B[N,K]^T.  CTA tile 128x128, 256 thr.
// PASS=3: Ahi*Bhi + Alo*Bhi + Ahi*Blo (error ~2^-22)
// PASS=1: Ahi*Bhi only               (error ~1.1e-4 realized; budget 1e-3)
// MODE 0: store fp32. MODE 1: fp32 + fp16 hi/lo split to g_tknhi/lo.
// MODE 2: A rows are l-major (m' = l*2048+bs); out[bs*20+l] =
//         tanh(acc + T1[bs] + sum_t a[m,t]*Lab2[l,t] + b5)
// ---------------------------------------------------------------------------
template <int MODE, int PASS>
__global__ __launch_bounds__(256, 2) void tgemm(
    const __half* __restrict__ Ahi, const __half* __restrict__ Alo, int lda,
    const __half* __restrict__ Bhi, const __half* __restrict__ Blo, int ldb,
    float* __restrict__ C, int Kd,
    const float* __restrict__ b5)
{
    extern __shared__ char smem[];
    const uint32_t sb = smem_u32(smem);
    const int tid = threadIdx.x;
    const int wid = tid >> 5, lid = tid & 31;
    const int n0 = blockIdx.x * 128, m0 = blockIdx.y * 128;

    const int wm = wid & 1;        // 0..1  -> 64-row slab
    const int wn = wid >> 1;       // 0..3  -> 32-col slab
    const int g  = lid >> 2;       // group id
    const int t4 = lid & 3;        // thread in group

    const int arow = wm * 64 + (lid & 15);
    const int acol = (lid >> 4) * 8;
    const int brow = wn * 32 + (lid & 7);
    const int bcol = ((lid >> 3) & 1) * 8;

    const int lrow = tid >> 3;
    const int lc8  = (tid & 7) * 8;

    const int NCp = Kd >> 6;
    const int NC  = NCp * PASS;

    float acc[4][4][4];
    #pragma unroll
    for (int i = 0; i < 4; i++)
        #pragma unroll
        for (int j = 0; j < 4; j++)
            #pragma unroll
            for (int r = 0; r < 4; r++) acc[i][j][r] = 0.0f;

    auto load_chunk = [&](int c, int s) {
        const int pass = (PASS == 1) ? 0 : ((c >= 2 * NCp) ? 2 : (c >= NCp ? 1 : 0));
        const int k0 = (c - pass * NCp) * 64;
        const __half* Ap = (pass == 1) ? Alo : Ahi;
        const __half* Bp = (pass == 2) ? Blo : Bhi;
        const uint32_t aB = sb + s * STAGEB;
        const uint32_t bB = sb + 36864 + s * STAGEB;
        #pragma unroll
        for (int p = 0; p < 4; p++) {
            const int row = lrow + p * 32;
            const uint32_t da = aB + (uint32_t)row * 144 + lc8 * 2;
            const void* ga = Ap + (size_t)(m0 + row) * lda + k0 + lc8;
            asm volatile("cp.async.cg.shared.global [%0], [%1], 16;" :: "r"(da), "l"(ga));
            const uint32_t db = bB + (uint32_t)row * 144 + lc8 * 2;
            const void* gb = Bp + (size_t)(n0 + row) * ldb + k0 + lc8;
            asm volatile("cp.async.cg.shared.global [%0], [%1], 16;" :: "r"(db), "l"(gb));
        }
        asm volatile("cp.async.commit_group;" ::: "memory");
    };

    auto compute = [&](int s) {
        const uint32_t aB = sb + s * STAGEB;
        const uint32_t bB = sb + 36864 + s * STAGEB;
        #pragma unroll
        for (int kk = 0; kk < 4; kk++) {
            uint32_t af[4][4], bf[4][2];
            #pragma unroll
            for (int i = 0; i < 4; i++) {
                const uint32_t ad = aB + (uint32_t)(arow + i * 16) * 144
                                  + (uint32_t)(kk * 16 + acol) * 2;
                asm volatile("ldmatrix.sync.aligned.m8n8.x4.shared.b16 {%0,%1,%2,%3}, [%4];"
                    : "=r"(af[i][0]), "=r"(af[i][1]), "=r"(af[i][2]), "=r"(af[i][3])
                    : "r"(ad));
            }
            #pragma unroll
            for (int j = 0; j < 4; j++) {
                const uint32_t bd = bB + (uint32_t)(brow + j * 8) * 144
                                  + (uint32_t)(kk * 16 + bcol) * 2;
                asm volatile("ldmatrix.sync.aligned.m8n8.x2.shared.b16 {%0,%1}, [%2];"
                    : "=r"(bf[j][0]), "=r"(bf[j][1]) : "r"(bd));
            }
            #pragma unroll
            for (int i = 0; i < 4; i++)
                #pragma unroll
                for (int j = 0; j < 4; j++)
                    asm volatile(
                        "mma.sync.aligned.m16n8k16.row.col.f32.f16.f16.f32 "
                        "{%0,%1,%2,%3}, {%4,%5,%6,%7}, {%8,%9}, {%0,%1,%2,%3};"
                        : "+f"(acc[i][j][0]), "+f"(acc[i][j][1]),
                          "+f"(acc[i][j][2]), "+f"(acc[i][j][3])
                        : "r"(af[i][0]), "r"(af[i][1]), "r"(af[i][2]), "r"(af[i][3]),
                          "r"(bf[j][0]), "r"(bf[j][1]));
        }
    };

    load_chunk(0, 0);
    for (int c = 0; c < NC; c++) {
        if (c + 1 < NC) {
            load_chunk(c + 1, (c + 1) & 1);
            asm volatile("cp.async.wait_group 1;" ::: "memory");
        } else {
            asm volatile("cp.async.wait_group 0;" ::: "memory");
        }
        __syncthreads();
        compute(c & 1);
        __syncthreads();
    }

    // ---------------- epilogue ----------------
    if (MODE == 2) {
        const int l   = m0 >> 11;        // 128 | 2048 so each tile is one l
        const int bsb = m0 & 2047;
        float* sLab = (float*)smem;          // [8][128]
        float* sB5  = sLab + 8 * 128;        // [128]
        float* sAv  = sB5 + 128;             // [128][8]
        for (int idx = tid; idx < 1024; idx += 256) {
            const int t = idx >> 7, o = idx & 127;
            sLab[idx] = g_Lab2[(size_t)(l * LSn + t) * Hn + n0 + o];
        }
        if (tid < 128) sB5[tid] = b5[n0 + tid];
        for (int idx = tid; idx < 1024; idx += 256) {
            const int r = idx >> 3, t = idx & 7;
            sAv[idx] = g_a[((size_t)(bsb + r) * Ln + l) * LSn + t];
        }
        __syncthreads();
        #pragma unroll
        for (int i = 0; i < 4; i++) {
            #pragma unroll
            for (int j = 0; j < 4; j++) {
                const int col = wn * 32 + j * 8 + 2 * t4;
                #pragma unroll
                for (int h = 0; h < 2; h++) {
                    const int rl = wm * 64 + i * 16 + g + h * 8;
                    const int bs = bsb + rl;
                    const float2 t1 = *(const float2*)(g_T1 + (size_t)bs * Hn + n0 + col);
                    float v0 = acc[i][j][h * 2]     + t1.x + sB5[col];
                    float v1 = acc[i][j][h * 2 + 1] + t1.y + sB5[col + 1];
                    const float* av = sAv + rl * 8;
                    #pragma unroll
                    for (int t = 0; t < 8; t++) {
                        const float at = av[t];
                        v0 += at * sLab[t * 128 + col];
                        v1 += at * sLab[t * 128 + col + 1];
                    }
                    float2 res = make_float2(tanhf(v0), tanhf(v1));
                    *(float2*)(C + ((size_t)bs * Ln + l) * Hn + n0 + col) = res;
                }
            }
        }
    } else {
        #pragma unroll
        for (int i = 0; i < 4; i++) {
            #pragma unroll
            for (int j = 0; j < 4; j++) {
                const int col = wn * 32 + j * 8 + 2 * t4;
                #pragma unroll
                for (int h = 0; h < 2; h++) {
                    const int m = m0 + wm * 64 + i * 16 + g + h * 8;
                    const float v0 = acc[i][j][h * 2];
                    const float v1 = acc[i][j][h * 2 + 1];
                    *(float2*)(C + (size_t)m * Hn + n0 + col) = make_float2(v0, v1);
                    if (MODE == 1) {
                        const size_t o = (size_t)m * Hn + n0 + col;
                        __half h0 = __float2half_rn(v0);
                        __half h1 = __float2half_rn(v1);
                        __half l0 = __float2half_rn(v0 - __half2float(h0));
                        __half l1 = __float2half_rn(v1 - __half2float(h1));
                        *(__half2*)(g_tknhi + o) = __halves2half2(h0, h1);
                        *(__half2*)(g_tknlo + o) = __halves2half2(l0, l1);
                    }
                }
            }
        }
    }
}

// ---------------------------------------------------------------------------
// fp32 -> fp16 hi/lo split, float4-vectorized (Kc % 4 == 0 at all call sites)
// ---------------------------------------------------------------------------
__global__ __launch_bounds__(256) void split_k4(
    const float* __restrict__ src, int ld,
    __half* __restrict__ hi, __half* __restrict__ lo,
    int Mr, int Kc)
{
    int q = blockIdx.x * 256 + threadIdx.x;       // quad index
    int nq = (Mr * Kc) >> 2;
    if (q >= nq) return;
    int kq = Kc >> 2;
    int r = q / kq, cq = q - r * kq;
    const float4 v = *(const float4*)(src + (size_t)r * ld + cq * 4);
    __half h0 = __float2half_rn(v.x), h1 = __float2half_rn(v.y);
    __half h2 = __float2half_rn(v.z), h3 = __float2half_rn(v.w);
    __half2 ph0 = __halves2half2(h0, h1), ph1 = __halves2half2(h2, h3);
    uint2 hp;
    hp.x = *reinterpret_cast<uint32_t*>(&ph0);
    hp.y = *reinterpret_cast<uint32_t*>(&ph1);
    *(uint2*)(hi + (size_t)q * 4) = hp;
    if (lo) {
        __half2 pl0 = __halves2half2(__float2half_rn(v.x - __half2float(h0)),
                                     __float2half_rn(v.y - __half2float(h1)));
        __half2 pl1 = __halves2half2(__float2half_rn(v.z - __half2float(h2)),
                                     __float2half_rn(v.w - __half2float(h3)));
        uint2 lp;
        lp.x = *reinterpret_cast<uint32_t*>(&pl0);
        lp.y = *reinterpret_cast<uint32_t*>(&pl1);
        *(uint2*)(lo + (size_t)q * 4) = lp;
    }
}

// ---------------------------------------------------------------------------
// Small guarded SGEMM, 32x32 tile (high CTA count): C[M,N] = A[M,K]*B[N,K]^T
// ---------------------------------------------------------------------------
__global__ __launch_bounds__(256) void sgemm32(
    const float* __restrict__ A, int lda,
    const float* __restrict__ Bm, int ldb,
    float* __restrict__ C, int ldc,
    int M, int N, int K)
{
    __shared__ float As[32][33];
    __shared__ float Bs[32][33];
    const int m0 = blockIdx.x * 32;
    const int n0 = blockIdx.y * 32;
    const int tid = threadIdx.x;
    const int tr = tid >> 4;     // 0..15
    const int tc = tid & 15;     // 0..15
    float acc[2][2] = {};

    for (int k0 = 0; k0 < K; k0 += 32) {
        #pragma unroll
        for (int p = 0; p < 4; p++) {
            int idx = tid + p * 256;
            int r = idx >> 5;
            int kk = idx & 31;
            int gk = k0 + kk;
            int gm = m0 + r;
            int gn = n0 + r;
            As[kk][r] = (gm < M && gk < K) ? A[(size_t)gm * lda + gk] : 0.0f;
            Bs[kk][r] = (gn < N && gk < K) ? Bm[(size_t)gn * ldb + gk] : 0.0f;
        }
        __syncthreads();
        #pragma unroll
        for (int kk = 0; kk < 32; kk++) {
            float a0 = As[kk][tr * 2], a1 = As[kk][tr * 2 + 1];
            float b0 = Bs[kk][tc * 2], b1 = Bs[kk][tc * 2 + 1];
            acc[0][0] += a0 * b0; acc[0][1] += a0 * b1;
            acc[1][0] += a1 * b0; acc[1][1] += a1 * b1;
        }
        __syncthreads();
    }
    #pragma unroll
    for (int i = 0; i < 2; i++) {
        int gm = m0 + tr * 2 + i;
        if (gm >= M) continue;
        #pragma unroll
        for (int j = 0; j < 2; j++) {
            int gn = n0 + tc * 2 + j;
            if (gn < N) C[(size_t)gm * ldc + gn] = acc[i][j];
        }
    }
}

// ---------------------------------------------------------------------------
// Softmax over label tokens + b_in
// ---------------------------------------------------------------------------
__global__ __launch_bounds__(256) void softmax_a_kernel(
    const float* __restrict__ label_mask,
    const float* __restrict__ input_mask)
{
    int m = blockIdx.x * 256 + threadIdx.x;
    if (m >= MTOT) return;
    int bs = m / Ln;
    int l = m - bs * Ln;
    float sc[LSn];
    float mx = -INFINITY;
    #pragma unroll
    for (int t = 0; t < LSn; t++) {
        float v = g_scores[(size_t)bs * (Ln * LSn) + l * LSn + t]
                + (1.0f - label_mask[l * LSn + t]) * NEGV;
        sc[t] = v;
        mx = fmaxf(mx, v);
    }
    float sum = 0.0f;
    #pragma unroll
    for (int t = 0; t < LSn; t++) { sc[t] = __expf(sc[t] - mx); sum += sc[t]; }
    float inv = 1.0f / sum;
    #pragma unroll
    for (int t = 0; t < LSn; t++) g_a[(size_t)m * LSn + t] = sc[t] * inv;
    g_bin[m] = mx + (1.0f - input_mask[bs]) * NEGV;
}

// ---------------------------------------------------------------------------
// Softmax over S + q2c
// ---------------------------------------------------------------------------
__global__ __launch_bounds__(256) void q2c_kernel()
{
    int b = blockIdx.x / Ln;
    int l = blockIdx.x - b * Ln;
    int s = threadIdx.x;
    __shared__ float red[256];
    __shared__ float w[256];

    float v = g_bin[(size_t)(b * Sn + s) * Ln + l];
    red[s] = v; __syncthreads();
    for (int off = 128; off > 0; off >>= 1) {
        if (s < off) red[s] = fmaxf(red[s], red[s + off]);
        __syncthreads();
    }
    float mx = red[0]; __syncthreads();
    float e = __expf(v - mx);
    red[s] = e; __syncthreads();
    for (int off = 128; off > 0; off >>= 1) {
        if (s < off) red[s] += red[s + off];
        __syncthreads();
    }
    float inv = 1.0f / red[0];
    w[s] = e * inv;
    __syncthreads();

    for (int h = s; h < Hn; h += 256) {
        float acc = 0.0f;
        #pragma unroll 8
        for (int ss = 0; ss < Sn; ss++)
            acc += w[ss] * g_tkn[(size_t)(b * Sn + ss) * Hn + h];
        g_q2c[(size_t)(b * Ln + l) * Hn + h] = acc;
    }
}

// ---------------------------------------------------------------------------
// Build fused A operand as fp16 (hi only), L-MAJOR rows (m' = l*2048+bs):
//   Af[m', h]      = tkn*c2q   (h in [0,768))
//   Af[m', 768+h]  = tkn*q2c
// ---------------------------------------------------------------------------
__global__ __launch_bounds__(256) void afused_kernel()
{
    int l   = blockIdx.x;
    int bs0 = blockIdx.y * 16;
    int b   = bs0 / Sn;
    int tid = threadIdx.x;

    __shared__ float labs[LSn * Hn];
    __shared__ float qv[Hn];
    __shared__ float av[16][LSn];

    for (int idx = tid; idx < LSn * Hn; idx += 256)
        labs[idx] = g_lab[(size_t)l * LSn * Hn + idx];
    for (int idx = tid; idx < Hn; idx += 256)
        qv[idx] = g_q2c[(size_t)(b * Ln + l) * Hn + idx];
    for (int idx = tid; idx < 16 * LSn; idx += 256) {
        int i = idx >> 3, t = idx & 7;
        av[i][t] = g_a[((size_t)(bs0 + i) * Ln + l) * LSn + t];
    }
    __syncthreads();

    const int hc = tid * 4;          // threads 0..191 active (192*4 = 768)
    for (int i = 0; i < 16; i++) {
        int bs = bs0 + i;
        size_t m = (size_t)l * BSn + bs;     // l-major row
        if (hc < Hn) {
            float a0 = av[i][0], a1 = av[i][1], a2 = av[i][2], a3 = av[i][3];
            float a4 = av[i][4], a5 = av[i][5], a6 = av[i][6], a7 = av[i][7];
            const float4 tv = *(const float4*)(g_tkn + (size_t)bs * Hn + hc);
            const float4 qv4 = *(const float4*)(qv + hc);
            float4 c = make_float4(0.f, 0.f, 0.f, 0.f);
            #pragma unroll
            for (int t = 0; t < LSn; t++) {
                const float at = (t == 0) ? a0 : (t == 1) ? a1 : (t == 2) ? a2 :
                                 (t == 3) ? a3 : (t == 4) ? a4 : (t == 5) ? a5 :
                                 (t == 6) ? a6 : a7;
                const float4 lb = *(const float4*)(labs + t * Hn + hc);
                c.x += at * lb.x; c.y += at * lb.y;
                c.z += at * lb.z; c.w += at * lb.w;
            }
            float4 v1 = make_float4(tv.x * c.x, tv.y * c.y, tv.z * c.z, tv.w * c.w);
            float4 v2 = make_float4(tv.x * qv4.x, tv.y * qv4.y, tv.z * qv4.z, tv.w * qv4.w);
            __half* Ah = g_Afhi + m * 1536;
            *(uint2*)(Ah + hc)      = pack4(v1);
            *(uint2*)(Ah + Hn + hc) = pack4(v2);
        }
    }
}

// ---------------------------------------------------------------------------
extern "C" void kernel_launch(void* const* d_in, const int* in_sizes, int n_in,
                              void* d_out, int out_size)
{
    const float* token = (const float*)d_in[0];
    const float* labe  = (const float*)d_in[1];
    const float* imask = (const float*)d_in[2];
    const float* lmask = (const float*)d_in[3];
    const float* W1    = (const float*)d_in[4];
    const float* W2    = (const float*)d_in[5];
    const float* W5    = (const float*)d_in[6];
    const float* b5    = (const float*)d_in[7];
    float* out = (float*)d_out;

    float *p_tkn, *p_lab, *p_T1, *p_Lab2, *p_scores;
    __half *p_tokhi, *p_toklo, *p_tknhi, *p_tknlo;
    __half *p_W1hi, *p_W1lo, *p_W5ahi, *p_W5alo, *p_Bhi, *p_Afhi;
    cudaGetSymbolAddress((void**)&p_tkn,    g_tkn);
    cudaGetSymbolAddress((void**)&p_lab,    g_lab);
    cudaGetSymbolAddress((void**)&p_T1,     g_T1);
    cudaGetSymbolAddress((void**)&p_Lab2,   g_Lab2);
    cudaGetSymbolAddress((void**)&p_scores, g_scores);
    cudaGetSymbolAddress((void**)&p_tokhi,  g_tokhi);
    cudaGetSymbolAddress((void**)&p_toklo,  g_toklo);
    cudaGetSymbolAddress((void**)&p_tknhi,  g_tknhi);
    cudaGetSymbolAddress((void**)&p_tknlo,  g_tknlo);
    cudaGetSymbolAddress((void**)&p_W1hi,   g_W1hi);
    cudaGetSymbolAddress((void**)&p_W1lo,   g_W1lo);
    cudaGetSymbolAddress((void**)&p_W5ahi,  g_W5ahi);
    cudaGetSymbolAddress((void**)&p_W5alo,  g_W5alo);
    cudaGetSymbolAddress((void**)&p_Bhi,    g_Bhi);
    cudaGetSymbolAddress((void**)&p_Afhi,   g_Afhi);

    cudaFuncSetAttribute((const void*)tgemm<0,3>, cudaFuncAttributeMaxDynamicSharedMemorySize, SMEM_SZ);
    cudaFuncSetAttribute((const void*)tgemm<1,3>, cudaFuncAttributeMaxDynamicSharedMemorySize, SMEM_SZ);
    cudaFuncSetAttribute((const void*)tgemm<2,1>, cudaFuncAttributeMaxDynamicSharedMemorySize, SMEM_SZ);

    // splits (fp16 hi/lo; W5cd hi-only), float4-vectorized
    split_k4<<<(BSn * Hn / 4 + 255) / 256, 256>>>(token, Hn, p_tokhi, p_toklo, BSn, Hn);
    split_k4<<<(Hn * Hn / 4 + 255) / 256, 256>>>(W1, Hn, p_W1hi, p_W1lo, Hn, Hn);
    split_k4<<<(Hn * Hn / 4 + 255) / 256, 256>>>(W5, 4 * Hn, p_W5ahi, p_W5alo, Hn, Hn);
    split_k4<<<(Hn * 2 * Hn / 4 + 255) / 256, 256>>>(W5 + 2 * Hn, 4 * Hn, p_Bhi, (__half*)nullptr, Hn, 2 * Hn);

    // lab = label_embs @ W2^T   [160,768] K=300 (fp32, 120 CTAs)
    sgemm32<<<dim3(5, 24), 256>>>(labe, En, W2, En, p_lab, Hn, Ln * LSn, Hn, En);
    // tkn = token @ W1^T (HMMA 3-pass, fp32 out + fp16 hi/lo split)
    tgemm<1,3><<<dim3(6, 16), 256, SMEM_SZ>>>(p_tokhi, p_toklo, Hn, p_W1hi, p_W1lo, Hn,
                                              p_tkn, Hn, nullptr);
    // T1 = tkn @ W5a^T (HMMA 3-pass)
    tgemm<0,3><<<dim3(6, 16), 256, SMEM_SZ>>>(p_tknhi, p_tknlo, Hn, p_W5ahi, p_W5alo, Hn,
                                              p_T1, Hn, nullptr);
    // Lab2 = lab @ W5b^T   [160,768] K=768 (fp32, 120 CTAs)
    sgemm32<<<dim3(5, 24), 256>>>(p_lab, Hn, W5 + Hn, 4 * Hn, p_Lab2, Hn, Ln * LSn, Hn, Hn);
    // scores = tkn @ lab^T [2048,160] K=768 (fp32, 320 CTAs)
    sgemm32<<<dim3(64, 5), 256>>>(p_tkn, Hn, p_lab, Hn, p_scores, Ln * LSn,
                                  BSn, Ln * LSn, Hn);
    // softmaxes
    softmax_a_kernel<<<MTOT / 256, 256>>>(lmask, imask);
    q2c_kernel<<<Bn * Ln, 256>>>();
    // fused A operand (fp16 hi, l-major)
    afused_kernel<<<dim3(Ln, BSn / 16), 256>>>();
    // big fused GEMM (HMMA single-pass) + epilogue
    tgemm<2,1><<<dim3(6, 320), 256, SMEM_SZ>>>(p_Afhi, (const __half*)nullptr, 2 * Hn,
                                               p_Bhi, (const __half*)nullptr, 2 * Hn,
                                               out, 2 * Hn, b5);
}